// round 1
// baseline (speedup 1.0000x reference)
#include <cuda_runtime.h>
#include <math.h>

#define N_CLS 8192
#define FEAT  512
#define BATCH 1024
#define NBLK  64          // 8192 / 128
#define BM    128
#define BK    16
#define LDA   (BM + 4)    // padded smem stride (floats)
#define TEMP_INV 10.0f
#define NEG_CNT  8191.0f

// ---- static device scratch (no allocations allowed) ----
__device__ float g_protos[N_CLS * FEAT];          // 16 MB updated prototypes
__device__ float g_partial[NBLK * N_CLS];         // [slice][row] exp-sum partials, 2 MB
__device__ int   g_next[BATCH];
__device__ int   g_head[BATCH];
__device__ float g_blocksum[32];

// ------------------------------------------------------------------
// 1) copy prototypes into scratch
// ------------------------------------------------------------------
__global__ void copy_protos(const float* __restrict__ p) {
    int n = N_CLS * FEAT / 4;
    float4*       dst = (float4*)g_protos;
    const float4* src = (const float4*)p;
    for (int i = blockIdx.x * blockDim.x + threadIdx.x; i < n;
         i += gridDim.x * blockDim.x)
        dst[i] = src[i];
}

// ------------------------------------------------------------------
// 2) chain link precompute: head[s], next[s] per sample
// ------------------------------------------------------------------
__global__ void prep_chains(const int* __restrict__ labels) {
    int s = blockIdx.x * blockDim.x + threadIdx.x;
    if (s >= BATCH) return;
    int l = labels[s];
    int head = 1;
    for (int t = 0; t < s; ++t)
        if (labels[t] == l) { head = 0; break; }
    int nxt = -1;
    for (int t = s + 1; t < BATCH; ++t)
        if (labels[t] == l) { nxt = t; break; }
    g_next[s] = nxt;
    g_head[s] = head;
}

// ------------------------------------------------------------------
// 3) EMA update: one warp per chain head, vector in registers
// ------------------------------------------------------------------
__global__ void ema_update(const float* __restrict__ feats,
                           const int*   __restrict__ labels) {
    int warp = (blockIdx.x * blockDim.x + threadIdx.x) >> 5;
    int lane = threadIdx.x & 31;
    if (warp >= BATCH) return;
    if (!g_head[warp]) return;

    int l = labels[warp];
    float* row = g_protos + (size_t)l * FEAT;

    float p[16];
#pragma unroll
    for (int t = 0; t < 16; ++t) p[t] = row[lane + 32 * t];

    int cur = warp;
    while (cur >= 0) {
        const float* f = feats + (size_t)cur * FEAT;
        float ss = 0.f;
#pragma unroll
        for (int t = 0; t < 16; ++t) {
            p[t] = p[t] * 0.95f + f[lane + 32 * t] * 0.05f;
            ss += p[t] * p[t];
        }
#pragma unroll
        for (int o = 16; o > 0; o >>= 1)
            ss += __shfl_xor_sync(0xffffffffu, ss, o);
        float inv = 1.0f / fmaxf(sqrtf(ss), 1e-12f);
#pragma unroll
        for (int t = 0; t < 16; ++t) p[t] *= inv;
        cur = g_next[cur];
    }
#pragma unroll
    for (int t = 0; t < 16; ++t) row[lane + 32 * t] = p[t];
}

// ------------------------------------------------------------------
// 4) symmetric pairwise GEMM + exp row/col sums
//    block b -> upper-triangular tile (bi, bj), bi <= bj
// ------------------------------------------------------------------
__global__ __launch_bounds__(256, 2)
void pairwise_expsum(void) {
    int b = blockIdx.x;
    int bi = 0;
    while (b >= NBLK - bi) { b -= NBLK - bi; ++bi; }
    int bj = bi + b;

    __shared__ float smem[2 * BK * LDA];
    float* As = smem;
    float* Bs = smem + BK * LDA;

    int tid = threadIdx.x;
    int tx = tid & 15;
    int ty = tid >> 4;

    float acc[8][8];
#pragma unroll
    for (int i = 0; i < 8; ++i)
#pragma unroll
        for (int j = 0; j < 8; ++j) acc[i][j] = 0.f;

    const float* Ag = g_protos + (size_t)bi * BM * FEAT;
    const float* Bg = g_protos + (size_t)bj * BM * FEAT;

    int lr = tid >> 2;         // 0..63
    int lc = (tid & 3) * 4;    // 0,4,8,12

    for (int k0 = 0; k0 < FEAT; k0 += BK) {
#pragma unroll
        for (int h = 0; h < 2; ++h) {
            int r = lr + h * 64;
            float4 va = *(const float4*)(Ag + (size_t)r * FEAT + k0 + lc);
            float4 vb = *(const float4*)(Bg + (size_t)r * FEAT + k0 + lc);
            As[(lc + 0) * LDA + r] = va.x;
            As[(lc + 1) * LDA + r] = va.y;
            As[(lc + 2) * LDA + r] = va.z;
            As[(lc + 3) * LDA + r] = va.w;
            Bs[(lc + 0) * LDA + r] = vb.x;
            Bs[(lc + 1) * LDA + r] = vb.y;
            Bs[(lc + 2) * LDA + r] = vb.z;
            Bs[(lc + 3) * LDA + r] = vb.w;
        }
        __syncthreads();
#pragma unroll
        for (int kk = 0; kk < BK; ++kk) {
            float af[8], bf[8];
            float4 a0 = *(float4*)&As[kk * LDA + ty * 8];
            float4 a1 = *(float4*)&As[kk * LDA + ty * 8 + 4];
            float4 b0 = *(float4*)&Bs[kk * LDA + tx * 8];
            float4 b1 = *(float4*)&Bs[kk * LDA + tx * 8 + 4];
            af[0]=a0.x; af[1]=a0.y; af[2]=a0.z; af[3]=a0.w;
            af[4]=a1.x; af[5]=a1.y; af[6]=a1.z; af[7]=a1.w;
            bf[0]=b0.x; bf[1]=b0.y; bf[2]=b0.z; bf[3]=b0.w;
            bf[4]=b1.x; bf[5]=b1.y; bf[6]=b1.z; bf[7]=b1.w;
#pragma unroll
            for (int i = 0; i < 8; ++i)
#pragma unroll
                for (int j = 0; j < 8; ++j)
                    acc[i][j] += af[i] * bf[j];
        }
        __syncthreads();
    }

    // ---- epilogue: exp, mask diagonal, row/col sums ----
    float rs[8], cs[8];
#pragma unroll
    for (int i = 0; i < 8; ++i) { rs[i] = 0.f; cs[i] = 0.f; }

    int baseI = bi * BM + ty * 8;
    int baseJ = bj * BM + tx * 8;
#pragma unroll
    for (int i = 0; i < 8; ++i)
#pragma unroll
        for (int j = 0; j < 8; ++j) {
            float e = __expf(acc[i][j] * TEMP_INV);
            if (bi == bj && (baseI + i) == (baseJ + j)) e = 0.f;
            rs[i] += e;
            cs[j] += e;
        }

    // reduce row sums over tx (lanes 0..15 within each half-warp)
#pragma unroll
    for (int i = 0; i < 8; ++i) {
        float v = rs[i];
        v += __shfl_xor_sync(0xffffffffu, v, 1);
        v += __shfl_xor_sync(0xffffffffu, v, 2);
        v += __shfl_xor_sync(0xffffffffu, v, 4);
        v += __shfl_xor_sync(0xffffffffu, v, 8);
        rs[i] = v;
    }
    if (tx == 0) {
#pragma unroll
        for (int i = 0; i < 8; ++i)
            g_partial[(size_t)bj * N_CLS + bi * BM + ty * 8 + i] = rs[i];
    }

    // column sums -> contributions for rows in the bj tile (symmetry)
    if (bi != bj) {
        __syncthreads();
#pragma unroll
        for (int j = 0; j < 8; ++j)
            smem[(tx * 8 + j) * 17 + ty] = cs[j];   // 128*17 = 2176 <= 4224 floats
        __syncthreads();
        if (tid < BM) {
            float s = 0.f;
#pragma unroll
            for (int t = 0; t < 16; ++t) s += smem[tid * 17 + t];
            g_partial[(size_t)bi * N_CLS + bj * BM + tid] = s;
        }
    }
}

// ------------------------------------------------------------------
// 5) per-row log-mean-exp + partial mean reduction
// ------------------------------------------------------------------
__global__ void row_reduce(void) {
    int row = blockIdx.x * blockDim.x + threadIdx.x;   // 32 blocks * 256
    float s = 0.f;
#pragma unroll 8
    for (int p = 0; p < NBLK; ++p) s += g_partial[(size_t)p * N_CLS + row];
    float v = logf(s * (1.0f / NEG_CNT));

    __shared__ float red[256];
    red[threadIdx.x] = v;
    __syncthreads();
    for (int o = 128; o > 0; o >>= 1) {
        if (threadIdx.x < o) red[threadIdx.x] += red[threadIdx.x + o];
        __syncthreads();
    }
    if (threadIdx.x == 0) g_blocksum[blockIdx.x] = red[0];
}

__global__ void final_reduce(float* __restrict__ out) {
    int lane = threadIdx.x;
    float s = (lane < 32) ? g_blocksum[lane] : 0.f;
#pragma unroll
    for (int o = 16; o > 0; o >>= 1)
        s += __shfl_xor_sync(0xffffffffu, s, o);
    if (lane == 0) out[0] = s * (1.0f / (float)N_CLS);  // T/baseT == 1
}

// ------------------------------------------------------------------
extern "C" void kernel_launch(void* const* d_in, const int* in_sizes, int n_in,
                              void* d_out, int out_size) {
    const float* features   = (const float*)d_in[0];   // [1024, 512] f32
    const int*   labels     = (const int*)d_in[1];     // [1024] i32
    const float* prototypes = (const float*)d_in[2];   // [8192, 512] f32
    float*       out        = (float*)d_out;

    copy_protos<<<2048, 256>>>(prototypes);
    prep_chains<<<4, 256>>>(labels);
    ema_update<<<BATCH / 8, 256>>>(features, labels);
    pairwise_expsum<<<NBLK * (NBLK + 1) / 2, 256>>>();   // 2080 tiles
    row_reduce<<<32, 256>>>();
    final_reduce<<<1, 32>>>(out);
}

// round 4
// speedup vs baseline: 5.0094x; 5.0094x over previous
#include <cuda_runtime.h>
#include <cuda_bf16.h>
#include <math.h>
#include <stdint.h>

#define N_CLS 8192
#define FEAT  512
#define BATCH 1024
#define NBLK  64          // 8192 / 128
#define BM    128
#define NEG_CNT  8191.0f

// K chunking: 64 bf16 elems (128 B rows -> SW128 swizzle)
#define KC        64
#define NCHUNK    (FEAT / KC)        // 8
#define STAGES    3
#define A_BYTES   (BM * KC * 2)      // 16384
#define STAGE_BYTES (2 * A_BYTES)    // 32768
#define DYN_SMEM  (STAGES * STAGE_BYTES + 1024)

// ---- static device scratch ----
__device__ __nv_bfloat16 g_protos_bf[N_CLS * FEAT];   // 8 MB bf16 prototypes
__device__ float g_partial[NBLK * N_CLS];             // [slice][row] partials
__device__ int   g_next[BATCH];
__device__ int   g_head[BATCH];
__device__ float g_blocksum[32];

// ================= helpers =================
__device__ __forceinline__ uint32_t smem_u32(const void* p) {
    uint32_t r;
    asm("{ .reg .u64 t; cvta.to.shared.u64 t, %1; cvt.u32.u64 %0, t; }"
        : "=r"(r) : "l"(p));
    return r;
}
#define CP_ASYNC16(dst, src) \
    asm volatile("cp.async.cg.shared.global [%0], [%1], 16;" :: "r"(dst), "l"(src) : "memory")
#define CP_COMMIT() asm volatile("cp.async.commit_group;" ::: "memory")
#define CP_WAIT(N)  asm volatile("cp.async.wait_group %0;" :: "n"(N) : "memory")

#define LDSM_X4(r0, r1, r2, r3, addr) \
    asm volatile("ldmatrix.sync.aligned.m8n8.x4.shared.b16 {%0,%1,%2,%3}, [%4];" \
                 : "=r"(r0), "=r"(r1), "=r"(r2), "=r"(r3) : "r"(addr))

#define MMA_16816(d, a, b0, b1) \
    asm volatile("mma.sync.aligned.m16n8k16.row.col.f32.bf16.bf16.f32 " \
                 "{%0,%1,%2,%3}, {%4,%5,%6,%7}, {%8,%9}, {%0,%1,%2,%3};" \
                 : "+f"((d)[0]), "+f"((d)[1]), "+f"((d)[2]), "+f"((d)[3]) \
                 : "r"((a)[0]), "r"((a)[1]), "r"((a)[2]), "r"((a)[3]), \
                   "r"(b0), "r"(b1))

__device__ __forceinline__ uint32_t sw128(uint32_t off) {
    return off ^ ((off >> 3) & 0x70);
}

// FMA-pipe exp(10*s): exp2 via magic-round + degree-5 poly, rel err ~2e-6
__device__ __forceinline__ float fast_exp_t10(float s) {
    float y = s * 14.4269504089f;                 // s * 10 * log2(e)
    float t = y + 12582912.0f;                    // 2^23 * 1.5 magic round
    int   k = __float_as_int(t) - 0x4B400000;
    float f = y - (t - 12582912.0f);              // in [-0.5, 0.5]
    float p = 0.0013333558f;
    p = fmaf(p, f, 0.0096181291f);
    p = fmaf(p, f, 0.0555041087f);
    p = fmaf(p, f, 0.2402265069f);
    p = fmaf(p, f, 0.6931471806f);
    p = fmaf(p, f, 1.0f);
    return __int_as_float((k + 127) << 23) * p;
}

// ------------------------------------------------------------------
// 1) convert all prototypes fp32 -> bf16
// ------------------------------------------------------------------
__global__ void convert_protos(const float* __restrict__ p) {
    int i = blockIdx.x * blockDim.x + threadIdx.x;     // 1,048,576 float4s
    float4 v = ((const float4*)p)[i];
    __nv_bfloat162* dst = (__nv_bfloat162*)g_protos_bf;
    dst[2 * i + 0] = __floats2bfloat162_rn(v.x, v.y);
    dst[2 * i + 1] = __floats2bfloat162_rn(v.z, v.w);
}

// ------------------------------------------------------------------
// 2) chain link precompute
// ------------------------------------------------------------------
__global__ void prep_chains(const int* __restrict__ labels) {
    __shared__ int lab[BATCH];
    for (int i = threadIdx.x; i < BATCH; i += 256) lab[i] = labels[i];
    __syncthreads();
    int s = blockIdx.x * 256 + threadIdx.x;
    int l = lab[s];
    int head = 1;
    for (int t = 0; t < s; ++t)
        if (lab[t] == l) { head = 0; break; }
    int nxt = -1;
    for (int t = s + 1; t < BATCH; ++t)
        if (lab[t] == l) { nxt = t; break; }
    g_next[s] = nxt;
    g_head[s] = head;
}

// ------------------------------------------------------------------
// 3) EMA update in fp32 registers, final row written as bf16
// ------------------------------------------------------------------
__global__ void ema_update(const float* __restrict__ feats,
                           const int*   __restrict__ labels,
                           const float* __restrict__ protos_in) {
    int warp = (blockIdx.x * blockDim.x + threadIdx.x) >> 5;
    int lane = threadIdx.x & 31;
    if (warp >= BATCH) return;
    if (!g_head[warp]) return;

    int l = labels[warp];
    const float* row = protos_in + (size_t)l * FEAT;

    float p[16];
#pragma unroll
    for (int t = 0; t < 16; ++t) p[t] = row[lane + 32 * t];

    int cur = warp;
    while (cur >= 0) {
        const float* f = feats + (size_t)cur * FEAT;
        float ss = 0.f;
#pragma unroll
        for (int t = 0; t < 16; ++t) {
            p[t] = p[t] * 0.95f + f[lane + 32 * t] * 0.05f;
            ss += p[t] * p[t];
        }
#pragma unroll
        for (int o = 16; o > 0; o >>= 1)
            ss += __shfl_xor_sync(0xffffffffu, ss, o);
        float inv = 1.0f / fmaxf(sqrtf(ss), 1e-12f);
#pragma unroll
        for (int t = 0; t < 16; ++t) p[t] *= inv;
        cur = g_next[cur];
    }
    __nv_bfloat16* rowb = g_protos_bf + (size_t)l * FEAT;
#pragma unroll
    for (int t = 0; t < 16; ++t) rowb[lane + 32 * t] = __float2bfloat16(p[t]);
}

// ------------------------------------------------------------------
// 4) HMMA pairwise tile kernel: 128x128x512 bf16 mma.sync + exp sums
// ------------------------------------------------------------------
__device__ __forceinline__ void load_chunk(int j, uint32_t base,
                                           const char* Ag, const char* Bg,
                                           int tid) {
    uint32_t stage = base + (uint32_t)(j % STAGES) * STAGE_BYTES;
    const char* Ac = Ag + j * (KC * 2);
    const char* Bc = Bg + j * (KC * 2);
#pragma unroll
    for (int q = 0; q < 4; ++q) {
        int seg = tid + q * 256;               // 0..1023
        int row = seg >> 3;
        int off = (seg & 7) * 16;
        uint32_t so = sw128((uint32_t)(row * 128 + off));
        CP_ASYNC16(stage + so,           Ac + (size_t)row * (FEAT * 2) + off);
        CP_ASYNC16(stage + A_BYTES + so, Bc + (size_t)row * (FEAT * 2) + off);
    }
    CP_COMMIT();
}

__global__ __launch_bounds__(256, 2)
void pairwise_tc(void) {
    extern __shared__ char dynsm[];
    __shared__ float s_rowpart[2][BM];
    __shared__ float s_colpart[4][BM];

    int tid  = threadIdx.x;
    int wid  = tid >> 5;
    int lane = tid & 31;
    int wm   = wid & 3;        // warp row block (32 rows)
    int wn   = wid >> 2;       // warp col block (64 cols)

    // decode triangular tile (bi <= bj)
    int b = blockIdx.x;
    int bi = 0;
    while (b >= NBLK - bi) { b -= NBLK - bi; ++bi; }
    int bj = bi + b;

    uint32_t base = (smem_u32(dynsm) + 1023u) & ~1023u;

    const char* Ag = (const char*)(g_protos_bf + (size_t)bi * BM * FEAT);
    const char* Bg = (const char*)(g_protos_bf + (size_t)bj * BM * FEAT);

    float acc[2][8][4];
#pragma unroll
    for (int mt = 0; mt < 2; ++mt)
#pragma unroll
        for (int nt = 0; nt < 8; ++nt)
#pragma unroll
            for (int r = 0; r < 4; ++r) acc[mt][nt][r] = 0.f;

    // prologue: 2 chunks in flight
    load_chunk(0, base, Ag, Bg, tid);
    load_chunk(1, base, Ag, Bg, tid);

    // per-lane ldmatrix address components (constant over loop)
    int lrow16 = lane & 15;        // row within 16-row group
    int khalf  = (lane >> 4) * 16; // byte offset: 8 elems * 2B

#define STEP(K)                                                                \
    {                                                                          \
        if ((K) == NCHUNK - 1) { CP_WAIT(0); } else { CP_WAIT(1); }            \
        __syncthreads();                                                       \
        if ((K) + 2 < NCHUNK) load_chunk((K) + 2, base, Ag, Bg, tid);          \
        uint32_t stA = base + (uint32_t)((K) % STAGES) * STAGE_BYTES;          \
        uint32_t stB = stA + A_BYTES;                                          \
        _Pragma("unroll")                                                      \
        for (int ks = 0; ks < 4; ++ks) {                                       \
            int kb = ks * 32 + khalf;  /* byte offset of k within chunk */     \
            uint32_t a[2][4];                                                  \
            _Pragma("unroll")                                                  \
            for (int mt = 0; mt < 2; ++mt) {                                   \
                int row = wm * 32 + mt * 16 + lrow16;                          \
                LDSM_X4(a[mt][0], a[mt][1], a[mt][2], a[mt][3],                \
                        stA + sw128((uint32_t)(row * 128 + kb)));              \
            }                                                                  \
            _Pragma("unroll")                                                  \
            for (int p = 0; p < 4; ++p) {                                      \
                uint32_t b0, b1, b2, b3;                                       \
                int nrow = wn * 64 + p * 16 + lrow16;                          \
                LDSM_X4(b0, b1, b2, b3,                                        \
                        stB + sw128((uint32_t)(nrow * 128 + kb)));             \
                _Pragma("unroll")                                              \
                for (int mt = 0; mt < 2; ++mt) {                               \
                    MMA_16816(acc[mt][2 * p + 0], a[mt], b0, b2);              \
                    MMA_16816(acc[mt][2 * p + 1], a[mt], b1, b3);              \
                }                                                              \
            }                                                                  \
        }                                                                      \
        __syncthreads();                                                       \
    }

    STEP(0) STEP(1) STEP(2) STEP(3) STEP(4) STEP(5) STEP(6) STEP(7)
#undef STEP

    // ---- epilogue: exp + masked diagonal + row/col sums ----
    float rs[2][2];   // [mt][row half]
    float cs[8][2];   // [nt][col parity]
#pragma unroll
    for (int mt = 0; mt < 2; ++mt) { rs[mt][0] = 0.f; rs[mt][1] = 0.f; }
#pragma unroll
    for (int nt = 0; nt < 8; ++nt) { cs[nt][0] = 0.f; cs[nt][1] = 0.f; }

    bool diag = (bi == bj);
    int r0base = wm * 32 + (lane >> 2);
    int c0base = wn * 64 + (lane & 3) * 2;
#pragma unroll
    for (int mt = 0; mt < 2; ++mt) {
        int row0 = r0base + mt * 16;
        int row1 = row0 + 8;
#pragma unroll
        for (int nt = 0; nt < 8; ++nt) {
            int col0 = c0base + nt * 8;
            int col1 = col0 + 1;
            float e0 = fast_exp_t10(acc[mt][nt][0]);
            float e1 = fast_exp_t10(acc[mt][nt][1]);
            float e2 = fast_exp_t10(acc[mt][nt][2]);
            float e3 = fast_exp_t10(acc[mt][nt][3]);
            if (diag) {
                if (row0 == col0) e0 = 0.f;
                if (row0 == col1) e1 = 0.f;
                if (row1 == col0) e2 = 0.f;
                if (row1 == col1) e3 = 0.f;
            }
            rs[mt][0] += e0 + e1;
            rs[mt][1] += e2 + e3;
            cs[nt][0] += e0 + e2;
            cs[nt][1] += e1 + e3;
        }
    }

    // row sums: reduce over the 4 column-lane groups (lane&3)
#pragma unroll
    for (int mt = 0; mt < 2; ++mt)
#pragma unroll
        for (int h = 0; h < 2; ++h) {
            float v = rs[mt][h];
            v += __shfl_xor_sync(0xffffffffu, v, 1);
            v += __shfl_xor_sync(0xffffffffu, v, 2);
            if ((lane & 3) == 0)
                s_rowpart[wn][wm * 32 + mt * 16 + h * 8 + (lane >> 2)] = v;
        }

    // col sums: reduce over the 8 row-lane groups (lane>>2)
#pragma unroll
    for (int nt = 0; nt < 8; ++nt)
#pragma unroll
        for (int pb = 0; pb < 2; ++pb) {
            float v = cs[nt][pb];
            v += __shfl_xor_sync(0xffffffffu, v, 4);
            v += __shfl_xor_sync(0xffffffffu, v, 8);
            v += __shfl_xor_sync(0xffffffffu, v, 16);
            if (lane < 4)
                s_colpart[wm][wn * 64 + nt * 8 + lane * 2 + pb] = v;
        }
    __syncthreads();

    if (tid < BM) {
        float rtot = s_rowpart[0][tid] + s_rowpart[1][tid];
        g_partial[(size_t)bj * N_CLS + bi * BM + tid] = rtot;
        if (bi != bj) {
            float ctot = s_colpart[0][tid] + s_colpart[1][tid]
                       + s_colpart[2][tid] + s_colpart[3][tid];
            g_partial[(size_t)bi * N_CLS + bj * BM + tid] = ctot;
        }
    }
}

// ------------------------------------------------------------------
// 5) per-row log-mean-exp + reduction
// ------------------------------------------------------------------
__global__ void row_reduce(void) {
    int row = blockIdx.x * blockDim.x + threadIdx.x;   // 32 * 256 = 8192
    float s = 0.f;
#pragma unroll 8
    for (int p = 0; p < NBLK; ++p) s += g_partial[(size_t)p * N_CLS + row];
    float v = logf(s * (1.0f / NEG_CNT));

    __shared__ float red[256];
    red[threadIdx.x] = v;
    __syncthreads();
    for (int o = 128; o > 0; o >>= 1) {
        if (threadIdx.x < o) red[threadIdx.x] += red[threadIdx.x + o];
        __syncthreads();
    }
    if (threadIdx.x == 0) g_blocksum[blockIdx.x] = red[0];
}

__global__ void final_reduce(float* __restrict__ out) {
    int lane = threadIdx.x;
    float s = (lane < 32) ? g_blocksum[lane] : 0.f;
#pragma unroll
    for (int o = 16; o > 0; o >>= 1)
        s += __shfl_xor_sync(0xffffffffu, s, o);
    if (lane == 0) out[0] = s * (1.0f / (float)N_CLS);  // T/baseT == 1
}

// ------------------------------------------------------------------
extern "C" void kernel_launch(void* const* d_in, const int* in_sizes, int n_in,
                              void* d_out, int out_size) {
    const float* features   = (const float*)d_in[0];   // [1024, 512] f32
    const int*   labels     = (const int*)d_in[1];     // [1024] i32
    const float* prototypes = (const float*)d_in[2];   // [8192, 512] f32
    float*       out        = (float*)d_out;

    cudaFuncSetAttribute(pairwise_tc,
                         cudaFuncAttributeMaxDynamicSharedMemorySize, DYN_SMEM);

    convert_protos<<<4096, 256>>>(prototypes);
    prep_chains<<<4, 256>>>(labels);
    ema_update<<<BATCH / 8, 256>>>(features, labels, prototypes);
    pairwise_tc<<<NBLK * (NBLK + 1) / 2, 256, DYN_SMEM>>>();   // 2080 tiles
    row_reduce<<<32, 256>>>();
    final_reduce<<<1, 32>>>(out);
}

// round 6
// speedup vs baseline: 6.8638x; 1.3702x over previous
#include <cuda_runtime.h>
#include <cuda_bf16.h>
#include <math.h>
#include <stdint.h>

#define N_CLS 8192
#define FEAT  512
#define BATCH 1024
#define NBLK  64          // 8192 / 128
#define BM    128
#define NEG_CNT  8191.0f

// K chunking: 64 bf16 elems (128 B rows -> SW128 swizzle)
#define KC        64
#define NCHUNK    (FEAT / KC)        // 8
#define STAGES    3
#define A_BYTES   (BM * KC * 2)      // 16384
#define STAGE_BYTES (2 * A_BYTES)    // 32768
#define DYN_SMEM  (STAGES * STAGE_BYTES + 1024)

// ---- static device scratch ----
__device__ __nv_bfloat16 g_protos_bf[N_CLS * FEAT];   // 8 MB bf16 prototypes
__device__ float g_partial[NBLK * N_CLS];             // [slice][row] partials
__device__ float g_blocksum[32];
__device__ int   g_ctr = 0;

// ================= helpers =================
__device__ __forceinline__ uint32_t smem_u32(const void* p) {
    uint32_t r;
    asm("{ .reg .u64 t; cvta.to.shared.u64 t, %1; cvt.u32.u64 %0, t; }"
        : "=r"(r) : "l"(p));
    return r;
}
#define CP_ASYNC16(dst, src) \
    asm volatile("cp.async.cg.shared.global [%0], [%1], 16;" :: "r"(dst), "l"(src) : "memory")
#define CP_COMMIT() asm volatile("cp.async.commit_group;" ::: "memory")
#define CP_WAIT(N)  asm volatile("cp.async.wait_group %0;" :: "n"(N) : "memory")

#define LDSM_X4(r0, r1, r2, r3, addr) \
    asm volatile("ldmatrix.sync.aligned.m8n8.x4.shared.b16 {%0,%1,%2,%3}, [%4];" \
                 : "=r"(r0), "=r"(r1), "=r"(r2), "=r"(r3) : "r"(addr))

#define MMA_16816(d, a, b0, b1) \
    asm volatile("mma.sync.aligned.m16n8k16.row.col.f32.bf16.bf16.f32 " \
                 "{%0,%1,%2,%3}, {%4,%5,%6,%7}, {%8,%9}, {%0,%1,%2,%3};" \
                 : "+f"((d)[0]), "+f"((d)[1]), "+f"((d)[2]), "+f"((d)[3]) \
                 : "r"((a)[0]), "r"((a)[1]), "r"((a)[2]), "r"((a)[3]), \
                   "r"(b0), "r"(b1))

__device__ __forceinline__ uint32_t sw128(uint32_t off) {
    return off ^ ((off >> 3) & 0x70);
}

// FMA-pipe exp(10*s): exp2 via magic-round + degree-5 poly, rel err ~2e-6
__device__ __forceinline__ float fast_exp_t10(float s) {
    float y = s * 14.4269504089f;                 // s * 10 * log2(e)
    float t = y + 12582912.0f;                    // 2^23 * 1.5 magic round
    int   k = __float_as_int(t) - 0x4B400000;
    float f = y - (t - 12582912.0f);              // in [-0.5, 0.5]
    float p = 0.0013333558f;
    p = fmaf(p, f, 0.0096181291f);
    p = fmaf(p, f, 0.0555041087f);
    p = fmaf(p, f, 0.2402265069f);
    p = fmaf(p, f, 0.6931471806f);
    p = fmaf(p, f, 1.0f);
    return __int_as_float((k + 127) << 23) * p;
}

// ------------------------------------------------------------------
// 1) convert all prototypes fp32 -> bf16
// ------------------------------------------------------------------
__global__ void convert_protos(const float* __restrict__ p) {
    int i = blockIdx.x * blockDim.x + threadIdx.x;     // 1,048,576 float4s
    float4 v = ((const float4*)p)[i];
    __nv_bfloat162* dst = (__nv_bfloat162*)g_protos_bf;
    dst[2 * i + 0] = __floats2bfloat162_rn(v.x, v.y);
    dst[2 * i + 1] = __floats2bfloat162_rn(v.z, v.w);
}

// ------------------------------------------------------------------
// 2) EMA update with inline chain detection (one warp per sample;
//    only first-occurrence warps walk their label chain)
// ------------------------------------------------------------------
__global__ void ema_update(const float* __restrict__ feats,
                           const int*   __restrict__ labels,
                           const float* __restrict__ protos_in) {
    __shared__ int lab[BATCH];
    for (int i = threadIdx.x; i < BATCH; i += 256) lab[i] = labels[i];
    __syncthreads();

    int warp = (blockIdx.x * blockDim.x + threadIdx.x) >> 5;   // 0..1023
    int lane = threadIdx.x & 31;
    int l = lab[warp];

    // head test: any earlier occurrence of l?
    bool dup = false;
    for (int t = lane; t < warp; t += 32) dup |= (lab[t] == l);
    if (__ballot_sync(0xffffffffu, dup)) return;   // not a chain head

    const float* row = protos_in + (size_t)l * FEAT;
    float p[16];
#pragma unroll
    for (int t = 0; t < 16; ++t) p[t] = row[lane + 32 * t];

    int cur = warp;
    while (true) {
        const float* f = feats + (size_t)cur * FEAT;
        float ss = 0.f;
#pragma unroll
        for (int t = 0; t < 16; ++t) {
            p[t] = p[t] * 0.95f + f[lane + 32 * t] * 0.05f;
            ss += p[t] * p[t];
        }
#pragma unroll
        for (int o = 16; o > 0; o >>= 1)
            ss += __shfl_xor_sync(0xffffffffu, ss, o);
        float inv = 1.0f / fmaxf(sqrtf(ss), 1e-12f);
#pragma unroll
        for (int t = 0; t < 16; ++t) p[t] *= inv;

        // find next occurrence of l after cur
        int nxt = -1;
        for (int base = cur + 1; base < BATCH; base += 32) {
            int t = base + lane;
            bool m = (t < BATCH) && (lab[t] == l);
            unsigned bal = __ballot_sync(0xffffffffu, m);
            if (bal) { nxt = base + __ffs(bal) - 1; break; }
        }
        if (nxt < 0) break;
        cur = nxt;
    }
    __nv_bfloat16* rowb = g_protos_bf + (size_t)l * FEAT;
#pragma unroll
    for (int t = 0; t < 16; ++t) rowb[lane + 32 * t] = __float2bfloat16(p[t]);
}

// ------------------------------------------------------------------
// 3) HMMA pairwise tile kernel: 128x128x512 bf16 mma.sync + exp sums
// ------------------------------------------------------------------
__device__ __forceinline__ void load_chunk(int j, uint32_t base,
                                           const char* Ag, const char* Bg,
                                           int tid) {
    uint32_t stage = base + (uint32_t)(j % STAGES) * STAGE_BYTES;
    const char* Ac = Ag + j * (KC * 2);
    const char* Bc = Bg + j * (KC * 2);
#pragma unroll
    for (int q = 0; q < 4; ++q) {
        int seg = tid + q * 256;               // 0..1023
        int row = seg >> 3;
        int off = (seg & 7) * 16;
        uint32_t so = sw128((uint32_t)(row * 128 + off));
        CP_ASYNC16(stage + so,           Ac + (size_t)row * (FEAT * 2) + off);
        CP_ASYNC16(stage + A_BYTES + so, Bc + (size_t)row * (FEAT * 2) + off);
    }
    CP_COMMIT();
}

__global__ __launch_bounds__(256, 2)
void pairwise_tc(void) {
    extern __shared__ char dynsm[];
    __shared__ float s_rowpart[2][BM];
    __shared__ float s_colpart[4][BM];

    int tid  = threadIdx.x;
    int wid  = tid >> 5;
    int lane = tid & 31;
    int wm   = wid & 3;        // warp row block (32 rows)
    int wn   = wid >> 2;       // warp col block (64 cols)

    // decode triangular tile (bi <= bj)
    int b = blockIdx.x;
    int bi = 0;
    while (b >= NBLK - bi) { b -= NBLK - bi; ++bi; }
    int bj = bi + b;

    uint32_t base = (smem_u32(dynsm) + 1023u) & ~1023u;

    const char* Ag = (const char*)(g_protos_bf + (size_t)bi * BM * FEAT);
    const char* Bg = (const char*)(g_protos_bf + (size_t)bj * BM * FEAT);

    float acc[2][8][4];
#pragma unroll
    for (int mt = 0; mt < 2; ++mt)
#pragma unroll
        for (int nt = 0; nt < 8; ++nt)
#pragma unroll
            for (int r = 0; r < 4; ++r) acc[mt][nt][r] = 0.f;

    // ---- precomputed ldmatrix addressing ----
    // sw128(row*128 + kb) == row*128 + (kb ^ mask_row) because kb < 128.
    int lrow16 = lane & 15;        // row within 16-row group
    int khalf  = (lane >> 4) * 16; // byte offset of k-half
    uint32_t rowA[2], maskA[2], rowB[4], maskB[4];
#pragma unroll
    for (int mt = 0; mt < 2; ++mt) {
        uint32_t r = (uint32_t)(wm * 32 + mt * 16 + lrow16) * 128u;
        rowA[mt] = r; maskA[mt] = (r >> 3) & 0x70;
    }
#pragma unroll
    for (int p = 0; p < 4; ++p) {
        uint32_t r = (uint32_t)(wn * 64 + p * 16 + lrow16) * 128u;
        rowB[p] = r; maskB[p] = (r >> 3) & 0x70;
    }

    // prologue: 2 chunks in flight
    load_chunk(0, base, Ag, Bg, tid);
    load_chunk(1, base, Ag, Bg, tid);

    // one barrier per step: wait -> sync -> issue K+2 -> compute K
#define STEP(K)                                                                \
    {                                                                          \
        if ((K) == NCHUNK - 1) { CP_WAIT(0); } else { CP_WAIT(1); }            \
        __syncthreads();                                                       \
        if ((K) + 2 < NCHUNK) load_chunk((K) + 2, base, Ag, Bg, tid);          \
        uint32_t stA = base + (uint32_t)((K) % STAGES) * STAGE_BYTES;          \
        uint32_t stB = stA + A_BYTES;                                          \
        _Pragma("unroll")                                                      \
        for (int ks = 0; ks < 4; ++ks) {                                       \
            uint32_t kb = (uint32_t)(ks * 32 + khalf);                         \
            uint32_t a[2][4];                                                  \
            uint32_t bf[4][4];                                                 \
            _Pragma("unroll")                                                  \
            for (int mt = 0; mt < 2; ++mt)                                     \
                LDSM_X4(a[mt][0], a[mt][1], a[mt][2], a[mt][3],                \
                        stA + rowA[mt] + (kb ^ maskA[mt]));                    \
            _Pragma("unroll")                                                  \
            for (int p = 0; p < 4; ++p)                                        \
                LDSM_X4(bf[p][0], bf[p][1], bf[p][2], bf[p][3],                \
                        stB + rowB[p] + (kb ^ maskB[p]));                      \
            _Pragma("unroll")                                                  \
            for (int p = 0; p < 4; ++p) {                                      \
                _Pragma("unroll")                                              \
                for (int mt = 0; mt < 2; ++mt) {                               \
                    MMA_16816(acc[mt][2 * p + 0], a[mt], bf[p][0], bf[p][2]);  \
                    MMA_16816(acc[mt][2 * p + 1], a[mt], bf[p][1], bf[p][3]);  \
                }                                                              \
            }                                                                  \
        }                                                                      \
    }

    STEP(0) STEP(1) STEP(2) STEP(3) STEP(4) STEP(5) STEP(6) STEP(7)
#undef STEP

    // ---- epilogue: exp + masked diagonal + row/col sums ----
    float rs[2][2];   // [mt][row half]
    float cs[8][2];   // [nt][col parity]
#pragma unroll
    for (int mt = 0; mt < 2; ++mt) { rs[mt][0] = 0.f; rs[mt][1] = 0.f; }
#pragma unroll
    for (int nt = 0; nt < 8; ++nt) { cs[nt][0] = 0.f; cs[nt][1] = 0.f; }

    bool diag = (bi == bj);
    int r0base = wm * 32 + (lane >> 2);
    int c0base = wn * 64 + (lane & 3) * 2;
#pragma unroll
    for (int mt = 0; mt < 2; ++mt) {
        int row0 = r0base + mt * 16;
        int row1 = row0 + 8;
#pragma unroll
        for (int nt = 0; nt < 8; ++nt) {
            int col0 = c0base + nt * 8;
            int col1 = col0 + 1;
            float e0 = fast_exp_t10(acc[mt][nt][0]);
            float e1 = fast_exp_t10(acc[mt][nt][1]);
            float e2 = fast_exp_t10(acc[mt][nt][2]);
            float e3 = fast_exp_t10(acc[mt][nt][3]);
            if (diag) {
                if (row0 == col0) e0 = 0.f;
                if (row0 == col1) e1 = 0.f;
                if (row1 == col0) e2 = 0.f;
                if (row1 == col1) e3 = 0.f;
            }
            rs[mt][0] += e0 + e1;
            rs[mt][1] += e2 + e3;
            cs[nt][0] += e0 + e2;
            cs[nt][1] += e1 + e3;
        }
    }

    __syncthreads();   // dyn smem stages no longer needed; reuse static arrays

    // row sums: reduce over the 4 column-lane groups (lane&3)
#pragma unroll
    for (int mt = 0; mt < 2; ++mt)
#pragma unroll
        for (int h = 0; h < 2; ++h) {
            float v = rs[mt][h];
            v += __shfl_xor_sync(0xffffffffu, v, 1);
            v += __shfl_xor_sync(0xffffffffu, v, 2);
            if ((lane & 3) == 0)
                s_rowpart[wn][wm * 32 + mt * 16 + h * 8 + (lane >> 2)] = v;
        }

    // col sums: reduce over the 8 row-lane groups (lane>>2)
#pragma unroll
    for (int nt = 0; nt < 8; ++nt)
#pragma unroll
        for (int pb = 0; pb < 2; ++pb) {
            float v = cs[nt][pb];
            v += __shfl_xor_sync(0xffffffffu, v, 4);
            v += __shfl_xor_sync(0xffffffffu, v, 8);
            v += __shfl_xor_sync(0xffffffffu, v, 16);
            if (lane < 4)
                s_colpart[wm][wn * 64 + nt * 8 + lane * 2 + pb] = v;
        }
    __syncthreads();

    if (tid < BM) {
        float rtot = s_rowpart[0][tid] + s_rowpart[1][tid];
        g_partial[(size_t)bj * N_CLS + bi * BM + tid] = rtot;
        if (bi != bj) {
            float ctot = s_colpart[0][tid] + s_colpart[1][tid]
                       + s_colpart[2][tid] + s_colpart[3][tid];
            g_partial[(size_t)bi * N_CLS + bj * BM + tid] = ctot;
        }
    }
}

// ------------------------------------------------------------------
// 4) fused per-row log-mean-exp + deterministic final reduction
// ------------------------------------------------------------------
__global__ void reduce_all(float* __restrict__ out) {
    int row = blockIdx.x * blockDim.x + threadIdx.x;   // 32 * 256 = 8192
    float s = 0.f;
#pragma unroll 8
    for (int p = 0; p < NBLK; ++p) s += g_partial[(size_t)p * N_CLS + row];
    float v = logf(s * (1.0f / NEG_CNT));

    __shared__ float red[256];
    red[threadIdx.x] = v;
    __syncthreads();
    for (int o = 128; o > 0; o >>= 1) {
        if (threadIdx.x < o) red[threadIdx.x] += red[threadIdx.x + o];
        __syncthreads();
    }
    if (threadIdx.x == 0) {
        g_blocksum[blockIdx.x] = red[0];
        __threadfence();
        int c = atomicAdd(&g_ctr, 1);
        if (c == 31) {                 // last block: fixed-order final sum
            __threadfence();
            float t = 0.f;
#pragma unroll
            for (int i = 0; i < 32; ++i) t += g_blocksum[i];
            out[0] = t * (1.0f / (float)N_CLS);   // T/baseT == 1
            g_ctr = 0;                 // reset for next graph replay
        }
    }
}

// ------------------------------------------------------------------
extern "C" void kernel_launch(void* const* d_in, const int* in_sizes, int n_in,
                              void* d_out, int out_size) {
    const float* features   = (const float*)d_in[0];   // [1024, 512] f32
    const int*   labels     = (const int*)d_in[1];     // [1024] i32
    const float* prototypes = (const float*)d_in[2];   // [8192, 512] f32
    float*       out        = (float*)d_out;

    cudaFuncSetAttribute(pairwise_tc,
                         cudaFuncAttributeMaxDynamicSharedMemorySize, DYN_SMEM);

    convert_protos<<<4096, 256>>>(prototypes);
    ema_update<<<BATCH / 8, 256>>>(features, labels, prototypes);
    pairwise_tc<<<NBLK * (NBLK + 1) / 2, 256, DYN_SMEM>>>();   // 2080 tiles
    reduce_all<<<32, 256>>>(out);
}

// round 7
// speedup vs baseline: 6.9706x; 1.0156x over previous
#include <cuda_runtime.h>
#include <cuda_bf16.h>
#include <math.h>
#include <stdint.h>

#define N_CLS 8192
#define FEAT  512
#define BATCH 1024
#define NBLK  64          // 8192 / 128
#define BM    128
#define NEG_CNT  8191.0f

// K chunking: 64 bf16 elems (128 B rows -> SW128 swizzle)
#define KC        64
#define NCHUNK    (FEAT / KC)        // 8
#define STAGES    3
#define A_BYTES   (BM * KC * 2)      // 16384
#define STAGE_BYTES (2 * A_BYTES)    // 32768
#define DYN_SMEM  (STAGES * STAGE_BYTES + 1024)

#define RED_BLOCKS 128               // reduce_all grid

// ---- static device scratch ----
__device__ __nv_bfloat16 g_protos_bf[N_CLS * FEAT];   // 8 MB bf16 prototypes
__device__ float g_partial[NBLK * N_CLS];             // [slice][row] partials
__device__ float g_blocksum[RED_BLOCKS];
__device__ int   g_ctr = 0;

// ================= helpers =================
__device__ __forceinline__ uint32_t smem_u32(const void* p) {
    uint32_t r;
    asm("{ .reg .u64 t; cvta.to.shared.u64 t, %1; cvt.u32.u64 %0, t; }"
        : "=r"(r) : "l"(p));
    return r;
}
#define CP_ASYNC16(dst, src) \
    asm volatile("cp.async.cg.shared.global [%0], [%1], 16;" :: "r"(dst), "l"(src) : "memory")
#define CP_COMMIT() asm volatile("cp.async.commit_group;" ::: "memory")
#define CP_WAIT(N)  asm volatile("cp.async.wait_group %0;" :: "n"(N) : "memory")

#define LDSM_X4(r0, r1, r2, r3, addr) \
    asm volatile("ldmatrix.sync.aligned.m8n8.x4.shared.b16 {%0,%1,%2,%3}, [%4];" \
                 : "=r"(r0), "=r"(r1), "=r"(r2), "=r"(r3) : "r"(addr))

#define MMA_16816(d, a, b0, b1) \
    asm volatile("mma.sync.aligned.m16n8k16.row.col.f32.bf16.bf16.f32 " \
                 "{%0,%1,%2,%3}, {%4,%5,%6,%7}, {%8,%9}, {%0,%1,%2,%3};" \
                 : "+f"((d)[0]), "+f"((d)[1]), "+f"((d)[2]), "+f"((d)[3]) \
                 : "r"((a)[0]), "r"((a)[1]), "r"((a)[2]), "r"((a)[3]), \
                   "r"(b0), "r"(b1))

__device__ __forceinline__ uint32_t sw128(uint32_t off) {
    return off ^ ((off >> 3) & 0x70);
}

// FMA-pipe exp(10*s): exp2 via magic-round + degree-5 poly, rel err ~2e-6
__device__ __forceinline__ float fast_exp_t10(float s) {
    float y = s * 14.4269504089f;                 // s * 10 * log2(e)
    float t = y + 12582912.0f;                    // 2^23 * 1.5 magic round
    int   k = __float_as_int(t) - 0x4B400000;
    float f = y - (t - 12582912.0f);              // in [-0.5, 0.5]
    float p = 0.0013333558f;
    p = fmaf(p, f, 0.0096181291f);
    p = fmaf(p, f, 0.0555041087f);
    p = fmaf(p, f, 0.2402265069f);
    p = fmaf(p, f, 0.6931471806f);
    p = fmaf(p, f, 1.0f);
    return __int_as_float((k + 127) << 23) * p;
}

// ------------------------------------------------------------------
// 1) convert all prototypes fp32 -> bf16
// ------------------------------------------------------------------
__global__ void convert_protos(const float* __restrict__ p) {
    int i = blockIdx.x * blockDim.x + threadIdx.x;     // 1,048,576 float4s
    float4 v = ((const float4*)p)[i];
    __nv_bfloat162* dst = (__nv_bfloat162*)g_protos_bf;
    dst[2 * i + 0] = __floats2bfloat162_rn(v.x, v.y);
    dst[2 * i + 1] = __floats2bfloat162_rn(v.z, v.w);
}

// ------------------------------------------------------------------
// 2) EMA update with inline chain detection (one warp per sample;
//    only first-occurrence warps walk their label chain)
// ------------------------------------------------------------------
__global__ void ema_update(const float* __restrict__ feats,
                           const int*   __restrict__ labels,
                           const float* __restrict__ protos_in) {
    __shared__ int lab[BATCH];
    for (int i = threadIdx.x; i < BATCH; i += 256) lab[i] = labels[i];
    __syncthreads();

    int warp = (blockIdx.x * blockDim.x + threadIdx.x) >> 5;   // 0..1023
    int lane = threadIdx.x & 31;
    int l = lab[warp];

    // head test: any earlier occurrence of l?
    bool dup = false;
    for (int t = lane; t < warp; t += 32) dup |= (lab[t] == l);
    if (__ballot_sync(0xffffffffu, dup)) return;   // not a chain head

    const float* row = protos_in + (size_t)l * FEAT;
    float p[16];
#pragma unroll
    for (int t = 0; t < 16; ++t) p[t] = row[lane + 32 * t];

    int cur = warp;
    while (true) {
        const float* f = feats + (size_t)cur * FEAT;
        float ss = 0.f;
#pragma unroll
        for (int t = 0; t < 16; ++t) {
            p[t] = p[t] * 0.95f + f[lane + 32 * t] * 0.05f;
            ss += p[t] * p[t];
        }
#pragma unroll
        for (int o = 16; o > 0; o >>= 1)
            ss += __shfl_xor_sync(0xffffffffu, ss, o);
        float inv = 1.0f / fmaxf(sqrtf(ss), 1e-12f);
#pragma unroll
        for (int t = 0; t < 16; ++t) p[t] *= inv;

        // find next occurrence of l after cur
        int nxt = -1;
        for (int base = cur + 1; base < BATCH; base += 32) {
            int t = base + lane;
            bool m = (t < BATCH) && (lab[t] == l);
            unsigned bal = __ballot_sync(0xffffffffu, m);
            if (bal) { nxt = base + __ffs(bal) - 1; break; }
        }
        if (nxt < 0) break;
        cur = nxt;
    }
    __nv_bfloat16* rowb = g_protos_bf + (size_t)l * FEAT;
#pragma unroll
    for (int t = 0; t < 16; ++t) rowb[lane + 32 * t] = __float2bfloat16(p[t]);
}

// ------------------------------------------------------------------
// 3) HMMA pairwise tile kernel: 128x128x512 bf16 mma.sync + exp sums
// ------------------------------------------------------------------
__device__ __forceinline__ void load_chunk(int j, uint32_t base,
                                           const char* Ag, const char* Bg,
                                           int tid) {
    uint32_t stage = base + (uint32_t)(j % STAGES) * STAGE_BYTES;
    const char* Ac = Ag + j * (KC * 2);
    const char* Bc = Bg + j * (KC * 2);
#pragma unroll
    for (int q = 0; q < 4; ++q) {
        int seg = tid + q * 256;               // 0..1023
        int row = seg >> 3;
        int off = (seg & 7) * 16;
        uint32_t so = sw128((uint32_t)(row * 128 + off));
        CP_ASYNC16(stage + so,           Ac + (size_t)row * (FEAT * 2) + off);
        CP_ASYNC16(stage + A_BYTES + so, Bc + (size_t)row * (FEAT * 2) + off);
    }
    CP_COMMIT();
}

__global__ __launch_bounds__(256, 2)
void pairwise_tc(void) {
    extern __shared__ char dynsm[];
    __shared__ float s_rowpart[2][BM];
    __shared__ float s_colpart[4][BM];

    int tid  = threadIdx.x;
    int wid  = tid >> 5;
    int lane = tid & 31;
    int wm   = wid & 3;        // warp row block (32 rows)
    int wn   = wid >> 2;       // warp col block (64 cols)

    // decode triangular tile (bi <= bj)
    int b = blockIdx.x;
    int bi = 0;
    while (b >= NBLK - bi) { b -= NBLK - bi; ++bi; }
    int bj = bi + b;

    uint32_t base = (smem_u32(dynsm) + 1023u) & ~1023u;

    const char* Ag = (const char*)(g_protos_bf + (size_t)bi * BM * FEAT);
    const char* Bg = (const char*)(g_protos_bf + (size_t)bj * BM * FEAT);

    float acc[2][8][4];
#pragma unroll
    for (int mt = 0; mt < 2; ++mt)
#pragma unroll
        for (int nt = 0; nt < 8; ++nt)
#pragma unroll
            for (int r = 0; r < 4; ++r) acc[mt][nt][r] = 0.f;

    // ---- precomputed ldmatrix addressing ----
    // sw128(row*128 + kb) == row*128 + (kb ^ mask_row) because kb < 128.
    int lrow16 = lane & 15;        // row within 16-row group
    int khalf  = (lane >> 4) * 16; // byte offset of k-half
    uint32_t rowA[2], maskA[2], rowB[4], maskB[4];
#pragma unroll
    for (int mt = 0; mt < 2; ++mt) {
        uint32_t r = (uint32_t)(wm * 32 + mt * 16 + lrow16) * 128u;
        rowA[mt] = r; maskA[mt] = (r >> 3) & 0x70;
    }
#pragma unroll
    for (int p = 0; p < 4; ++p) {
        uint32_t r = (uint32_t)(wn * 64 + p * 16 + lrow16) * 128u;
        rowB[p] = r; maskB[p] = (r >> 3) & 0x70;
    }

    // prologue: 2 chunks in flight
    load_chunk(0, base, Ag, Bg, tid);
    load_chunk(1, base, Ag, Bg, tid);

    // one barrier per step: wait -> sync -> issue K+2 -> compute K
#define STEP(K)                                                                \
    {                                                                          \
        if ((K) == NCHUNK - 1) { CP_WAIT(0); } else { CP_WAIT(1); }            \
        __syncthreads();                                                       \
        if ((K) + 2 < NCHUNK) load_chunk((K) + 2, base, Ag, Bg, tid);          \
        uint32_t stA = base + (uint32_t)((K) % STAGES) * STAGE_BYTES;          \
        uint32_t stB = stA + A_BYTES;                                          \
        _Pragma("unroll")                                                      \
        for (int ks = 0; ks < 4; ++ks) {                                       \
            uint32_t kb = (uint32_t)(ks * 32 + khalf);                         \
            uint32_t a[2][4];                                                  \
            uint32_t bf[4][4];                                                 \
            _Pragma("unroll")                                                  \
            for (int mt = 0; mt < 2; ++mt)                                     \
                LDSM_X4(a[mt][0], a[mt][1], a[mt][2], a[mt][3],                \
                        stA + rowA[mt] + (kb ^ maskA[mt]));                    \
            _Pragma("unroll")                                                  \
            for (int p = 0; p < 4; ++p)                                        \
                LDSM_X4(bf[p][0], bf[p][1], bf[p][2], bf[p][3],                \
                        stB + rowB[p] + (kb ^ maskB[p]));                      \
            _Pragma("unroll")                                                  \
            for (int p = 0; p < 4; ++p) {                                      \
                _Pragma("unroll")                                              \
                for (int mt = 0; mt < 2; ++mt) {                               \
                    MMA_16816(acc[mt][2 * p + 0], a[mt], bf[p][0], bf[p][2]);  \
                    MMA_16816(acc[mt][2 * p + 1], a[mt], bf[p][1], bf[p][3]);  \
                }                                                              \
            }                                                                  \
        }                                                                      \
    }

    STEP(0) STEP(1) STEP(2) STEP(3) STEP(4) STEP(5) STEP(6) STEP(7)
#undef STEP

    // ---- epilogue: exp + masked diagonal + row/col sums ----
    float rs[2][2];   // [mt][row half]
    float cs[8][2];   // [nt][col parity]
#pragma unroll
    for (int mt = 0; mt < 2; ++mt) { rs[mt][0] = 0.f; rs[mt][1] = 0.f; }
#pragma unroll
    for (int nt = 0; nt < 8; ++nt) { cs[nt][0] = 0.f; cs[nt][1] = 0.f; }

    bool diag = (bi == bj);
    int r0base = wm * 32 + (lane >> 2);
    int c0base = wn * 64 + (lane & 3) * 2;
#pragma unroll
    for (int mt = 0; mt < 2; ++mt) {
        int row0 = r0base + mt * 16;
        int row1 = row0 + 8;
#pragma unroll
        for (int nt = 0; nt < 8; ++nt) {
            int col0 = c0base + nt * 8;
            int col1 = col0 + 1;
            float e0 = fast_exp_t10(acc[mt][nt][0]);
            float e1 = fast_exp_t10(acc[mt][nt][1]);
            float e2 = fast_exp_t10(acc[mt][nt][2]);
            float e3 = fast_exp_t10(acc[mt][nt][3]);
            if (diag) {
                if (row0 == col0) e0 = 0.f;
                if (row0 == col1) e1 = 0.f;
                if (row1 == col0) e2 = 0.f;
                if (row1 == col1) e3 = 0.f;
            }
            rs[mt][0] += e0 + e1;
            rs[mt][1] += e2 + e3;
            cs[nt][0] += e0 + e2;
            cs[nt][1] += e1 + e3;
        }
    }

    __syncthreads();   // dyn smem stages no longer needed; reuse static arrays

    // row sums: reduce over the 4 column-lane groups (lane&3)
#pragma unroll
    for (int mt = 0; mt < 2; ++mt)
#pragma unroll
        for (int h = 0; h < 2; ++h) {
            float v = rs[mt][h];
            v += __shfl_xor_sync(0xffffffffu, v, 1);
            v += __shfl_xor_sync(0xffffffffu, v, 2);
            if ((lane & 3) == 0)
                s_rowpart[wn][wm * 32 + mt * 16 + h * 8 + (lane >> 2)] = v;
        }

    // col sums: reduce over the 8 row-lane groups (lane>>2)
#pragma unroll
    for (int nt = 0; nt < 8; ++nt)
#pragma unroll
        for (int pb = 0; pb < 2; ++pb) {
            float v = cs[nt][pb];
            v += __shfl_xor_sync(0xffffffffu, v, 4);
            v += __shfl_xor_sync(0xffffffffu, v, 8);
            v += __shfl_xor_sync(0xffffffffu, v, 16);
            if (lane < 4)
                s_colpart[wm][wn * 64 + nt * 8 + lane * 2 + pb] = v;
        }
    __syncthreads();

    if (tid < BM) {
        float rtot = s_rowpart[0][tid] + s_rowpart[1][tid];
        g_partial[(size_t)bj * N_CLS + bi * BM + tid] = rtot;
        if (bi != bj) {
            float ctot = s_colpart[0][tid] + s_colpart[1][tid]
                       + s_colpart[2][tid] + s_colpart[3][tid];
            g_partial[(size_t)bi * N_CLS + bj * BM + tid] = ctot;
        }
    }
}

// ------------------------------------------------------------------
// 4) fused per-row log-mean-exp + deterministic final reduction
//    4 threads per row (quad in-warp), 16 slices each -> 32k threads
// ------------------------------------------------------------------
__global__ __launch_bounds__(256)
void reduce_all(float* __restrict__ out) {
    int tid  = threadIdx.x;
    int rloc = tid >> 2;                 // 0..63 row within block
    int q    = tid & 3;                  // slice quarter
    int row  = blockIdx.x * 64 + rloc;   // 128 blocks * 64 rows

    const float* base = g_partial + (size_t)q * 16 * N_CLS + row;
    float s = 0.f;
#pragma unroll
    for (int p = 0; p < 16; ++p) s += base[(size_t)p * N_CLS];

    // combine quad (fixed order via shfl tree)
    s += __shfl_xor_sync(0xffffffffu, s, 1);
    s += __shfl_xor_sync(0xffffffffu, s, 2);

    __shared__ float red[64];
    if (q == 0) red[rloc] = logf(s * (1.0f / NEG_CNT));
    __syncthreads();

    if (tid < 32) {
        float v = red[tid] + red[tid + 32];
#pragma unroll
        for (int o = 16; o > 0; o >>= 1)
            v += __shfl_xor_sync(0xffffffffu, v, o);
        if (tid == 0) {
            g_blocksum[blockIdx.x] = v;
            __threadfence();
            int c = atomicAdd(&g_ctr, 1);
            if (c == RED_BLOCKS - 1) {       // last block: fixed-order finish
                __threadfence();
                float t = 0.f;
#pragma unroll
                for (int i = 0; i < RED_BLOCKS; ++i) t += g_blocksum[i];
                out[0] = t * (1.0f / (float)N_CLS);   // T/baseT == 1
                g_ctr = 0;                   // reset for next graph replay
            }
        }
    }
}

// ------------------------------------------------------------------
extern "C" void kernel_launch(void* const* d_in, const int* in_sizes, int n_in,
                              void* d_out, int out_size) {
    const float* features   = (const float*)d_in[0];   // [1024, 512] f32
    const int*   labels     = (const int*)d_in[1];     // [1024] i32
    const float* prototypes = (const float*)d_in[2];   // [8192, 512] f32
    float*       out        = (float*)d_out;

    cudaFuncSetAttribute(pairwise_tc,
                         cudaFuncAttributeMaxDynamicSharedMemorySize, DYN_SMEM);

    convert_protos<<<4096, 256>>>(prototypes);
    ema_update<<<BATCH / 8, 256>>>(features, labels, prototypes);
    pairwise_tc<<<NBLK * (NBLK + 1) / 2, 256, DYN_SMEM>>>();   // 2080 tiles
    reduce_all<<<RED_BLOCKS, 256>>>(out);
}